// round 7
// baseline (speedup 1.0000x reference)
#include <cuda_runtime.h>
#include <cstdint>

// Problem constants
#define Bn 64
#define Sn 128
#define Tn 64
#define Fn 100
#define F3 300
#define EPSV 1e-7f

#define RTOT (Bn*Sn*Tn)          // 524288 rows of the big GEMM
#define TILE_R 32
#define NTILES (RTOT/TILE_R)     // 16384

// Scratch: xw[b,s,t,f] = x @ W + b_bias   (210 MB, static device global — allowed)
__device__ float g_xw[(size_t)RTOT * Fn];

// ---------------------------------------------------------------------------
// packed fp32x2 FMA (Blackwell f32x2 pipe)
__device__ __forceinline__ unsigned long long ffma2(unsigned long long a,
                                                    unsigned long long b,
                                                    unsigned long long c) {
    unsigned long long d;
    asm("fma.rn.f32x2 %0, %1, %2, %3;" : "=l"(d) : "l"(a), "l"(b), "l"(c));
    return d;
}

__device__ __forceinline__ float tanh_ap(float x) {
    float y;
    asm("tanh.approx.f32 %0, %1;" : "=f"(y) : "f"(x));
    return y;
}

// ---------------------------------------------------------------------------
// Kernel A: xw = x @ W + bias.  Persistent blocks, W resident in SMEM as
// float2 column-pairs, x values duplicated into both halves of a float2 so a
// single fma.rn.f32x2 does 2 output columns per issue slot.
//
// Block: 256 threads = (tx 32, ty 8). Tile: 32 rows x 100 cols, K = 100.
// Thread: 4 rows (ty + 8k) x 2 col-pairs (p0 = tx, p1 = min(tx+32,49)).
//
// SMEM layout (floats): ws2 = 5000 float2 = 10000 floats (40,000 B)
//                       xs2 = 3200 float2 =  6400 floats (25,600 B)
//                       total 16400 floats = 65,600 B  <-- was under-allocated (R4 fault)
__global__ void __launch_bounds__(256, 3)
xw_kernel(const float* __restrict__ x, const float* __restrict__ W,
          const float* __restrict__ bias) {
    extern __shared__ float smemA[];
    float2* ws2 = reinterpret_cast<float2*>(smemA);            // 100 x 50 float2
    float2* xs2 = reinterpret_cast<float2*>(smemA + 10000);    // 32 x 100 float2 (dup)

    const int tid = threadIdx.x;
    const int tx = tid & 31;
    const int ty = tid >> 5;

    // Load W once per block (flat copy; row of 100 floats == 50 float2 pairs)
    const float2* Wv = reinterpret_cast<const float2*>(W);
    for (int i = tid; i < 5000; i += 256) ws2[i] = Wv[i];

    const int p0 = tx;
    const int p1 = (tx + 32 < 50) ? (tx + 32) : 49;   // clamp (dup work, store masked)
    const bool p1v = (tx + 32) < 50;

    const unsigned long long* bias2 = reinterpret_cast<const unsigned long long*>(bias);
    const unsigned long long bias0 = __ldg(bias2 + p0);
    const unsigned long long bias1 = __ldg(bias2 + p1);

    for (int tile = blockIdx.x; tile < NTILES; tile += gridDim.x) {
        const float* xt = x + (size_t)tile * TILE_R * Fn;
        __syncthreads();   // protect xs2 from previous iteration's readers
        for (int i = tid; i < TILE_R * Fn; i += 256) {
            float v = xt[i];
            xs2[i] = make_float2(v, v);
        }
        __syncthreads();

        unsigned long long acc[4][2];
#pragma unroll
        for (int k = 0; k < 4; ++k) { acc[k][0] = bias0; acc[k][1] = bias1; }

        const unsigned long long* xsu = reinterpret_cast<const unsigned long long*>(xs2);
        const unsigned long long* wsu = reinterpret_cast<const unsigned long long*>(ws2);

#pragma unroll 2
        for (int g = 0; g < Fn; ++g) {
            const unsigned long long w0 = wsu[g * 50 + p0];
            const unsigned long long w1 = wsu[g * 50 + p1];
#pragma unroll
            for (int k = 0; k < 4; ++k) {
                const unsigned long long xv = xsu[(ty + 8 * k) * Fn + g];
                acc[k][0] = ffma2(xv, w0, acc[k][0]);
                acc[k][1] = ffma2(xv, w1, acc[k][1]);
            }
        }

        float* ob = g_xw + (size_t)tile * TILE_R * Fn;
#pragma unroll
        for (int k = 0; k < 4; ++k) {
            const int r = ty + 8 * k;
            *reinterpret_cast<unsigned long long*>(ob + r * Fn + 2 * p0) = acc[k][0];
            if (p1v)
                *reinterpret_cast<unsigned long long*>(ob + r * Fn + 2 * p1) = acc[k][1];
        }
    }
}

// ---------------------------------------------------------------------------
// Kernel B: per-batch sequential recurrence. 64 CTAs (one per batch element),
// 512 threads. Wx fully + Wh rows [0,88) in SMEM; Wh tail / W_context / bg
// stream from L2 (hot). x / xw tiles read from gmem with L2 prefetch of the
// next step issued by otherwise-idle warps.
#define WH_SMEM_ROWS 88

__global__ void __launch_bounds__(512, 1)
rec_kernel(const float* __restrict__ x, const float* __restrict__ Wc,
           const float* __restrict__ u, const float* __restrict__ Wx,
           const float* __restrict__ Wh, const float* __restrict__ bg,
           float* __restrict__ out) {
    extern __shared__ float sm[];
    float* Wx_s  = sm;                     // 30000 floats
    float* Wh_s  = sm + 30000;             // 26400 floats (88 rows x 300)
    float* h_s   = sm + 56400;             // 100
    float* c_s   = h_s + 100;              // 100
    float* u_s   = c_s + 100;              // 100
    float* att_s = u_s + 100;              // 100
    float* a_s   = att_s + 100;            // 64 (ait, then normalized weights)
    float* gh_s  = a_s + 64;               // 300
    float* zr_s  = gh_s + 300;             // 200
    float* gxc_s = zr_s + 200;             // 100
    // total = 57464 floats = 229,856 bytes (< 232,448 B per-block limit)

    const int tid  = threadIdx.x;
    const int lane = tid & 31;
    const int wid  = tid >> 5;
    const int b    = blockIdx.x;

    for (int i = tid; i < Fn * F3; i += 512) Wx_s[i] = Wx[i];
    for (int i = tid; i < WH_SMEM_ROWS * F3; i += 512) Wh_s[i] = Wh[i];
    if (tid < Fn) { u_s[tid] = u[tid]; h_s[tid] = 0.0f; }

    const float* xb  = x    + (size_t)b * Sn * Tn * Fn;
    const float* xwb = g_xw + (size_t)b * Sn * Tn * Fn;
    float*       ob  = out  + (size_t)b * Sn * Fn;

    __syncthreads();

    for (int s = 0; s < Sn; ++s) {
        const float* xs_p = xb  + s * Tn * Fn;
        const float* xw_p = xwb + s * Tn * Fn;

        // ---- Phase A: gh = h @ Wh (300 thr) || c = h @ Wc (100 thr) || prefetch
        if (tid < F3) {
            const int j = tid;
            float a0 = 0.0f, a1 = 0.0f;
#pragma unroll 4
            for (int g = 0; g < WH_SMEM_ROWS; g += 2) {
                a0 += h_s[g]     * Wh_s[g * F3 + j];
                a1 += h_s[g + 1] * Wh_s[(g + 1) * F3 + j];
            }
#pragma unroll
            for (int g = WH_SMEM_ROWS; g < Fn; ++g)
                a0 += h_s[g] * __ldg(Wh + g * F3 + j);
            gh_s[j] = a0 + a1;
        } else if (tid < 400) {
            const int f = tid - F3;
            float a0 = 0.0f, a1 = 0.0f;
#pragma unroll 4
            for (int g = 0; g < Fn; g += 2) {
                a0 += h_s[g]     * __ldg(Wc + g * Fn + f);
                a1 += h_s[g + 1] * __ldg(Wc + (g + 1) * Fn + f);
            }
            c_s[f] = a0 + a1;
        } else if (s + 1 < Sn) {
            // L2 prefetch of next step's x / xw tiles (200 x 128B lines each)
            const char* nx = (const char*)(xb  + (s + 1) * Tn * Fn);
            const char* nw = (const char*)(xwb + (s + 1) * Tn * Fn);
            for (int l = tid - 400; l < 200; l += 112) {
                asm volatile("prefetch.global.L2 [%0];" :: "l"(nx + (size_t)l * 128));
                asm volatile("prefetch.global.L2 [%0];" :: "l"(nw + (size_t)l * 128));
            }
        }
        __syncthreads();

        // ---- Phase B: ait[t] = sum_f tanh(xw + c) * u  (one t per warp-iter)
        for (int t = wid; t < Tn; t += 16) {
            const float* row = xw_p + t * Fn;
            const int f = lane;
            float sum = tanh_ap(row[f]      + c_s[f])      * u_s[f]
                      + tanh_ap(row[f + 32] + c_s[f + 32]) * u_s[f + 32]
                      + tanh_ap(row[f + 64] + c_s[f + 64]) * u_s[f + 64];
            if (lane < 4)
                sum += tanh_ap(row[f + 96] + c_s[f + 96]) * u_s[f + 96];
#pragma unroll
            for (int o = 16; o > 0; o >>= 1)
                sum += __shfl_xor_sync(0xffffffffu, sum, o);
            if (lane == 0) a_s[t] = sum;
        }
        __syncthreads();

        // ---- Softmax-like: a = exp(ait) / (sum + EPS)   (warp 0)
        if (wid == 0) {
            const float e0 = __expf(a_s[lane]);
            const float e1 = __expf(a_s[lane + 32]);
            float tot = e0 + e1;
#pragma unroll
            for (int o = 16; o > 0; o >>= 1)
                tot += __shfl_xor_sync(0xffffffffu, tot, o);
            const float inv = 1.0f / (tot + EPSV);
            a_s[lane]      = e0 * inv;
            a_s[lane + 32] = e1 * inv;
        }
        __syncthreads();

        // ---- Phase C: attended[f] = sum_t a[t] * x[t,f]
        if (tid < Fn) {
            float a0 = 0.0f, a1 = 0.0f, a2 = 0.0f, a3 = 0.0f;
#pragma unroll 4
            for (int t = 0; t < Tn; t += 4) {
                a0 += a_s[t]     * __ldg(xs_p + t * Fn + tid);
                a1 += a_s[t + 1] * __ldg(xs_p + (t + 1) * Fn + tid);
                a2 += a_s[t + 2] * __ldg(xs_p + (t + 2) * Fn + tid);
                a3 += a_s[t + 3] * __ldg(xs_p + (t + 3) * Fn + tid);
            }
            att_s[tid] = (a0 + a1) + (a2 + a3);
        }
        __syncthreads();

        // ---- Phase D1: gates. j<200: zr = sigmoid(gx+gh). j in [200,300): gx only.
        if (tid < 200) {
            const int j = tid;
            float a0 = __ldg(bg + j) + gh_s[j], a1 = 0.0f;
#pragma unroll 4
            for (int g = 0; g < Fn; g += 2) {
                a0 += att_s[g]     * Wx_s[g * F3 + j];
                a1 += att_s[g + 1] * Wx_s[(g + 1) * F3 + j];
            }
            const float v = a0 + a1;
            zr_s[j] = 1.0f / (1.0f + __expf(-v));
        } else if (tid < F3) {
            const int j = tid;
            float a0 = __ldg(bg + j), a1 = 0.0f;
#pragma unroll 4
            for (int g = 0; g < Fn; g += 2) {
                a0 += att_s[g]     * Wx_s[g * F3 + j];
                a1 += att_s[g + 1] * Wx_s[(g + 1) * F3 + j];
            }
            gxc_s[j - 200] = a0 + a1;
        }
        __syncthreads();

        // ---- Phase D2: h = (1-z)*h + z*tanh(gxc + r*ghc); emit output
        if (tid < Fn) {
            const int f = tid;
            const float z  = zr_s[f];
            const float r  = zr_s[100 + f];
            const float ht = tanhf(gxc_s[f] + r * gh_s[200 + f]);
            const float hn = (1.0f - z) * h_s[f] + z * ht;
            ob[s * Fn + f] = hn;
            h_s[f] = hn;
        }
        __syncthreads();
    }
}

// ---------------------------------------------------------------------------
extern "C" void kernel_launch(void* const* d_in, const int* in_sizes, int n_in,
                              void* d_out, int out_size) {
    const float* x   = (const float*)d_in[0];
    const float* W   = (const float*)d_in[1];
    const float* Wc  = (const float*)d_in[2];
    const float* bb  = (const float*)d_in[3];
    const float* u   = (const float*)d_in[4];
    const float* Wx  = (const float*)d_in[5];
    const float* Wh  = (const float*)d_in[6];
    const float* bg  = (const float*)d_in[7];
    float* out = (float*)d_out;

    const int smemA = (10000 + 2 * TILE_R * Fn) * 4;   // 65,600 B (ws2 + xs2 as float2)
    const int smemB = 57464 * 4;                       // 229,856 B

    cudaFuncSetAttribute(xw_kernel, cudaFuncAttributeMaxDynamicSharedMemorySize, smemA);
    cudaFuncSetAttribute(rec_kernel, cudaFuncAttributeMaxDynamicSharedMemorySize, smemB);

    xw_kernel<<<444, 256, smemA>>>(x, W, bb);
    rec_kernel<<<Bn, 512, smemB>>>(x, Wc, u, Wx, Wh, bg, out);
}

// round 9
// speedup vs baseline: 1.6921x; 1.6921x over previous
#include <cuda_runtime.h>
#include <cstdint>

// Problem constants
#define Bn 64
#define Sn 128
#define Tn 64
#define Fn 100
#define F3 300
#define EPSV 1e-7f
#define THALF 32          // t-rows handled per CTA (t-split across the 2-CTA cluster)

// ---- SMEM layout (float offsets) --------------------------------------------
#define OFF_W     0        // W (x@W weight), 100x100, row-major  (10000)
#define OFF_WX    10000    // my 50 rows of Wx: [50r..50r+50) x 300 (15000)
#define OFF_WH    25000    // my 50 rows of Wh                     (15000)
#define OFF_WC    40000    // my 50 rows of W_context x 100        (5000)
#define OFF_RAW   45000    // x tile staging (32x100)              (3200)
#define OFF_DUP   48200    // x tile duplicated float2 (for f32x2) (6400)
#define OFF_H     54600    // h (full 100, replicated both CTAs)   (100)
#define OFF_U     54700    // u                                    (100)
#define OFF_BIAS  54800    // b (bias of x@W)                      (100)
#define OFF_BG    54900    // bg                                   (300)
#define OFF_CP    55200    // my partial of c=h@Wc                 (100)
#define OFF_CQ    55300    // peer's partial (pushed to me)        (100)
#define OFF_GHP   55400    // my partial of gh=h@Wh                (300)
#define OFF_GHQ   55700    // peer partial, DOUBLE-BUFFERED [2][300] (600)
#define OFF_GXP   56300    // my partial of gx=att@Wx              (300)
#define OFF_GXQ   56600    // peer partial                         (300)
#define OFF_ATTP  56900    // my attended partial (already /denom) (100)
#define OFF_ATTQ  57000    // peer attended partial                (100)
#define OFF_A     57100    // 32 local scores -> exp values        (32)
#define OFF_DEN   57132    // [0]=my exp-sum, [1]=peer exp-sum     (4)
#define SMEM_FLOATS 57136  // 228,544 bytes  (< 232,448 limit)

// ---------------------------------------------------------------------------
__device__ __forceinline__ unsigned long long ffma2(unsigned long long a,
                                                    unsigned long long b,
                                                    unsigned long long c) {
    unsigned long long d;
    asm("fma.rn.f32x2 %0, %1, %2, %3;" : "=l"(d) : "l"(a), "l"(b), "l"(c));
    return d;
}
__device__ __forceinline__ float tanh_ap(float x) {
    float y; asm("tanh.approx.f32 %0, %1;" : "=f"(y) : "f"(x)); return y;
}
__device__ __forceinline__ uint32_t s2u(const void* p) {
    return (uint32_t)__cvta_generic_to_shared(p);
}
// Store one float into the PEER CTA's smem at the same offset as `lptr`.
__device__ __forceinline__ void st_peer(float* lptr, uint32_t peer, float v) {
    uint32_t a = s2u(lptr), rem;
    asm volatile("mapa.shared::cluster.u32 %0, %1, %2;" : "=r"(rem) : "r"(a), "r"(peer));
    asm volatile("st.shared::cluster.f32 [%0], %1;" :: "r"(rem), "f"(v));
}
// barrier.cluster.arrive has release, .wait has acquire semantics -> orders
// all st_peer writes before the rendezvous against all reads after it.
#define CLUSTER_SYNC() do { \
    asm volatile("barrier.cluster.arrive.aligned;" ::: "memory"); \
    asm volatile("barrier.cluster.wait.aligned;"   ::: "memory"); \
} while (0)

// ---------------------------------------------------------------------------
// Fused kernel: 64 clusters x 2 CTAs, 512 threads/CTA, 1 CTA/SM.
// Per step: [repack x -> dup] [X-GEMM(xw, reg-resident) || gh,c GEMVs]
//           sync1 [scores+softmax-partial] sync2 [attended] sync3
//           [gates GEMV] sync4 [h update, both CTAs redundantly].
__global__ void __launch_bounds__(512, 1) __cluster_dims__(2, 1, 1)
fused_kernel(const float* __restrict__ x,   const float* __restrict__ Wg,
             const float* __restrict__ Wc,  const float* __restrict__ bias,
             const float* __restrict__ u,   const float* __restrict__ Wx,
             const float* __restrict__ Wh,  const float* __restrict__ bg,
             float* __restrict__ out)
{
    extern __shared__ float sm[];
    const int tid  = threadIdx.x;
    const int lane = tid & 31;
    const int wid  = tid >> 5;
    uint32_t rank; asm("mov.u32 %0, %%cluster_ctarank;" : "=r"(rank));
    const uint32_t peer = rank ^ 1u;
    const int r = (int)rank;
    const int b = blockIdx.x >> 1;

    // ---- prologue: weights into SMEM (all reads contiguous) ----
    for (int i = tid; i < 10000; i += 512) sm[OFF_W  + i] = Wg[i];
    for (int i = tid; i < 15000; i += 512) sm[OFF_WX + i] = Wx[r * 15000 + i];
    for (int i = tid; i < 15000; i += 512) sm[OFF_WH + i] = Wh[r * 15000 + i];
    for (int i = tid; i <  5000; i += 512) sm[OFF_WC + i] = Wc[r *  5000 + i];
    if (tid < 100) { sm[OFF_U + tid] = u[tid]; sm[OFF_BIAS + tid] = bias[tid];
                     sm[OFF_H + tid] = 0.0f; }
    if (tid < 300)   sm[OFF_BG + tid] = bg[tid];
    __syncthreads();

    const float* xbase = x + (size_t)b * Sn * Tn * Fn + (size_t)r * THALF * Fn;
    const uint32_t raw_s = s2u(&sm[OFF_RAW]);

    // stage x tile for s=0 (12800 B = 800 x 16B)
    for (int c = tid; c < 800; c += 512)
        asm volatile("cp.async.cg.shared.global [%0], [%1], 16;"
                     :: "r"(raw_s + c * 16), "l"(xbase + c * 4));
    asm volatile("cp.async.commit_group;" ::: "memory");

    for (int s = 0; s < Sn; ++s) {
        asm volatile("cp.async.wait_group 0;" ::: "memory");
        __syncthreads();                       // raw(s) ready; h(s-1) visible

        // ---- repack raw -> duplicated float2 (for fma.f32x2) ----
        for (int i = tid; i < THALF * Fn; i += 512) {
            const float v = sm[OFF_RAW + i];
            *reinterpret_cast<float2*>(&sm[OFF_DUP + 2 * i]) = make_float2(v, v);
        }
        __syncthreads();

        // ---- stage x tile for s+1 (overlaps everything below) ----
        if (s + 1 < Sn) {
            const float* src = xbase + (size_t)(s + 1) * Tn * Fn;
            for (int c = tid; c < 800; c += 512)
                asm volatile("cp.async.cg.shared.global [%0], [%1], 16;"
                             :: "r"(raw_s + c * 16), "l"(src + c * 4));
        }
        asm volatile("cp.async.commit_group;" ::: "memory");

        // ---- Phase X (warps 0-7): xw tile, register-resident ----
        //      || Phase A (warps 8-15): partial gh = h@Wh, partial c = h@Wc
        unsigned long long acc0[4], acc1[4];
        if (wid < 8) {
            const int pi = (lane < 25) ? lane : 24;   // 25 active pair-lanes
            const unsigned long long b0 =
                *reinterpret_cast<const unsigned long long*>(&sm[OFF_BIAS + 2 * pi]);
            const unsigned long long b1 =
                *reinterpret_cast<const unsigned long long*>(&sm[OFF_BIAS + 2 * pi + 50]);
#pragma unroll
            for (int k = 0; k < 4; ++k) { acc0[k] = b0; acc1[k] = b1; }
            const int tb = wid * 4;
#pragma unroll 4
            for (int g = 0; g < Fn; ++g) {
                const unsigned long long w0 =
                    *reinterpret_cast<const unsigned long long*>(&sm[OFF_W + g * 100 + 2 * pi]);
                const unsigned long long w1 =
                    *reinterpret_cast<const unsigned long long*>(&sm[OFF_W + g * 100 + 2 * pi + 50]);
#pragma unroll
                for (int k = 0; k < 4; ++k) {
                    const unsigned long long xv =
                        *reinterpret_cast<const unsigned long long*>(
                            &sm[OFF_DUP + 2 * ((tb + k) * Fn + g)]);
                    acc0[k] = ffma2(xv, w0, acc0[k]);
                    acc1[k] = ffma2(xv, w1, acc1[k]);
                }
            }
        } else {
            const int t2 = tid - 256;
            for (int j = t2; j < F3; j += 256) {
                float a0 = 0.0f, a1 = 0.0f;
#pragma unroll 5
                for (int gl = 0; gl < 50; gl += 2) {
                    a0 += sm[OFF_H + 50 * r + gl    ] * sm[OFF_WH + gl       * F3 + j];
                    a1 += sm[OFF_H + 50 * r + gl + 1] * sm[OFF_WH + (gl + 1) * F3 + j];
                }
                const float v = a0 + a1;
                sm[OFF_GHP + j] = v;
                st_peer(&sm[OFF_GHQ + (s & 1) * F3 + j], peer, v);
            }
            if (t2 < 100) {
                const int f = t2;
                float a0 = 0.0f, a1 = 0.0f;
#pragma unroll 5
                for (int gl = 0; gl < 50; gl += 2) {
                    a0 += sm[OFF_H + 50 * r + gl    ] * sm[OFF_WC + gl       * Fn + f];
                    a1 += sm[OFF_H + 50 * r + gl + 1] * sm[OFF_WC + (gl + 1) * Fn + f];
                }
                const float v = a0 + a1;
                sm[OFF_CP + f] = v;
                st_peer(&sm[OFF_CQ + f], peer, v);
            }
        }
        CLUSTER_SYNC();   // #1: gh & c partials exchanged

        // ---- Phase B (warps 0-7): scores from register-resident xw ----
        if (wid < 8) {
            const int tb = wid * 4;
#pragma unroll
            for (int k = 0; k < 4; ++k) {
                float sumv = 0.0f;
                if (lane < 25) {
                    const int f0 = 2 * lane, f2 = f0 + 50;
                    const float x0 = __uint_as_float((unsigned)(acc0[k] & 0xffffffffull));
                    const float x1 = __uint_as_float((unsigned)(acc0[k] >> 32));
                    const float x2 = __uint_as_float((unsigned)(acc1[k] & 0xffffffffull));
                    const float x3 = __uint_as_float((unsigned)(acc1[k] >> 32));
                    const float c0 = sm[OFF_CP + f0    ] + sm[OFF_CQ + f0    ];
                    const float c1 = sm[OFF_CP + f0 + 1] + sm[OFF_CQ + f0 + 1];
                    const float c2 = sm[OFF_CP + f2    ] + sm[OFF_CQ + f2    ];
                    const float c3 = sm[OFF_CP + f2 + 1] + sm[OFF_CQ + f2 + 1];
                    sumv = tanh_ap(x0 + c0) * sm[OFF_U + f0    ]
                         + tanh_ap(x1 + c1) * sm[OFF_U + f0 + 1]
                         + tanh_ap(x2 + c2) * sm[OFF_U + f2    ]
                         + tanh_ap(x3 + c3) * sm[OFF_U + f2 + 1];
                }
#pragma unroll
                for (int o = 16; o; o >>= 1)
                    sumv += __shfl_xor_sync(0xffffffffu, sumv, o);
                if (lane == 0) sm[OFF_A + tb + k] = sumv;
            }
        }
        __syncthreads();

        // ---- softmax partial (warp 15): exp + local denominator ----
        if (wid == 15) {
            const float e = __expf(sm[OFF_A + lane]);
            float tot = e;
#pragma unroll
            for (int o = 16; o; o >>= 1)
                tot += __shfl_xor_sync(0xffffffffu, tot, o);
            sm[OFF_A + lane] = e;
            if (lane == 0) { sm[OFF_DEN] = tot; st_peer(&sm[OFF_DEN + 1], peer, tot); }
        }
        CLUSTER_SYNC();   // #2: denominators exchanged

        // ---- Phase C: attended partial over my 32 t-rows (denom folded) ----
        if (tid < Fn) {
            const float inv = 1.0f / (sm[OFF_DEN] + sm[OFF_DEN + 1] + EPSV);
            float a0 = 0.f, a1 = 0.f, a2 = 0.f, a3 = 0.f;
#pragma unroll 4
            for (int t = 0; t < THALF; t += 4) {
                a0 += sm[OFF_A + t    ] * sm[OFF_DUP + 2 * ((t    ) * Fn + tid)];
                a1 += sm[OFF_A + t + 1] * sm[OFF_DUP + 2 * ((t + 1) * Fn + tid)];
                a2 += sm[OFF_A + t + 2] * sm[OFF_DUP + 2 * ((t + 2) * Fn + tid)];
                a3 += sm[OFF_A + t + 3] * sm[OFF_DUP + 2 * ((t + 3) * Fn + tid)];
            }
            const float v = ((a0 + a1) + (a2 + a3)) * inv;
            sm[OFF_ATTP + tid] = v;
            st_peer(&sm[OFF_ATTQ + tid], peer, v);
        }
        CLUSTER_SYNC();   // #3: attended partials exchanged

        // ---- Phase D: partial gx = att @ Wx (my 50 K-rows); bg folded in CTA0 ----
        if (tid < F3) {
            float acc = (r == 0) ? sm[OFF_BG + tid] : 0.0f;
#pragma unroll 2
            for (int gl = 0; gl < 50; ++gl) {
                const int f = 50 * r + gl;
                const float af = sm[OFF_ATTP + f] + sm[OFF_ATTQ + f];
                acc += af * sm[OFF_WX + gl * F3 + tid];
            }
            sm[OFF_GXP + tid] = acc;
            st_peer(&sm[OFF_GXQ + tid], peer, acc);
        }
        CLUSTER_SYNC();   // #4: gx partials exchanged

        // ---- Final: gates + h update (computed identically in BOTH CTAs) ----
        if (tid < Fn) {
            const int f  = tid;
            const int gq = OFF_GHQ + (s & 1) * F3;
            const float gz  = sm[OFF_GHP + f]       + sm[gq + f]
                            + sm[OFF_GXP + f]       + sm[OFF_GXQ + f];
            const float gr  = sm[OFF_GHP + 100 + f] + sm[gq + 100 + f]
                            + sm[OFF_GXP + 100 + f] + sm[OFF_GXQ + 100 + f];
            const float ghc = sm[OFF_GHP + 200 + f] + sm[gq + 200 + f];
            const float gxc = sm[OFF_GXP + 200 + f] + sm[OFF_GXQ + 200 + f];
            const float z   = 1.0f / (1.0f + __expf(-gz));
            const float rr  = 1.0f / (1.0f + __expf(-gr));
            const float ht  = tanhf(gxc + rr * ghc);
            const float hn  = (1.0f - z) * sm[OFF_H + f] + z * ht;
            sm[OFF_H + f] = hn;
            if (r == 0) out[((size_t)b * Sn + s) * Fn + f] = hn;
        }
        // h_s visibility for next step's Phase A is covered by the
        // wait_group + __syncthreads at the top of the loop.
    }
}

// ---------------------------------------------------------------------------
extern "C" void kernel_launch(void* const* d_in, const int* in_sizes, int n_in,
                              void* d_out, int out_size) {
    const float* x   = (const float*)d_in[0];
    const float* W   = (const float*)d_in[1];
    const float* Wc  = (const float*)d_in[2];
    const float* bb  = (const float*)d_in[3];
    const float* u   = (const float*)d_in[4];
    const float* Wx  = (const float*)d_in[5];
    const float* Wh  = (const float*)d_in[6];
    const float* bg  = (const float*)d_in[7];
    float* out = (float*)d_out;

    const int smem = SMEM_FLOATS * 4;   // 228,544 B
    cudaFuncSetAttribute(fused_kernel,
                         cudaFuncAttributeMaxDynamicSharedMemorySize, smem);
    fused_kernel<<<2 * Bn, 512, smem>>>(x, W, Wc, bb, u, Wx, Wh, bg, out);
}

// round 14
// speedup vs baseline: 1.8410x; 1.0880x over previous
#include <cuda_runtime.h>
#include <cstdint>

// Problem constants
#define Bn 64
#define Sn 128
#define Tn 64
#define Fn 100
#define F3 300
#define EPSV 1e-7f
#define THALF 32

typedef unsigned long long ull;

// ---- SMEM layout (float offsets) -------------------------------------------
// WT2: pair-transposed W for f32x2 g-pair GEMM. 50 g-pairs x 112 ull rows
//      (padded from 100 -> 112 so each 16-lane 8B load = one 128B line; pad=0).
#define OFF_WT2   0        // 50*112 ull = 11200 floats (44.8 KB), 128B-aligned
#define OFF_WX    11200    // my 50 rows of Wx  (15000)
#define OFF_WH    26200    // my 50 rows of Wh  (15000)
#define OFF_WC    41200    // my 50 rows of Wc  (5000)
#define OFF_RAW0  46200    // x tile buffer 0 (32x100)  (3200)
#define OFF_RAW1  49400    // x tile buffer 1           (3200)
#define OFF_H     52600    // h (full 100, replicated)  (100)
#define OFF_U     52700    // u                         (100)
#define OFF_BIAS  52800    // bias of x@W               (100)
#define OFF_BG    52900    // bg                        (300)
#define OFF_CP    53200    // my partial c=h@Wc         (100)
#define OFF_CQ    53300    // peer partial (pushed)     (100)
#define OFF_GHP   53400    // my partial gh=h@Wh        (300)
#define OFF_GHQ   53700    // peer partial, parity [2][300] (600)
#define OFF_GXP   54300    // my partial gx=att@Wx      (300)
#define OFF_GXQ   54600    // peer partial              (300)
#define OFF_ATTP  54900    // my attended partial       (100)
#define OFF_ATTQ  55000    // peer attended partial     (100)
#define OFF_ALOC  55100    // my 32 raw scores          (32)
#define OFF_APEER 55132    // peer 32 raw scores        (32)
#define OFF_EW    55164    // exp(own scores)/denom     (32)
#define SMEM_FLOATS 55200  // 220,800 bytes (< 232,448)

// ---------------------------------------------------------------------------
__device__ __forceinline__ ull ffma2(ull a, ull b, ull c) {
    ull d;
    asm("fma.rn.f32x2 %0, %1, %2, %3;" : "=l"(d) : "l"(a), "l"(b), "l"(c));
    return d;
}
__device__ __forceinline__ float tanh_ap(float x) {
    float y; asm("tanh.approx.f32 %0, %1;" : "=f"(y) : "f"(x)); return y;
}
__device__ __forceinline__ uint32_t s2u(const void* p) {
    return (uint32_t)__cvta_generic_to_shared(p);
}
__device__ __forceinline__ void st_peer(float* lptr, uint32_t peer, float v) {
    uint32_t a = s2u(lptr), rem;
    asm volatile("mapa.shared::cluster.u32 %0, %1, %2;" : "=r"(rem) : "r"(a), "r"(peer));
    asm volatile("st.shared::cluster.f32 [%0], %1;" :: "r"(rem), "f"(v));
}
// barrier.cluster.arrive has release, .wait acquire semantics.
#define CLUSTER_SYNC() do { \
    asm volatile("barrier.cluster.arrive.aligned;" ::: "memory"); \
    asm volatile("barrier.cluster.wait.aligned;"   ::: "memory"); \
} while (0)

// ---------------------------------------------------------------------------
// 64 clusters x 2 CTAs x 512 threads. Per step:
//  [X-GEMM on warps 0-3 (reg-resident xw) || gh,c GEMVs on warps 4-15]
//  csync1 [scores on warps 0-3, raw-score exchange] csync2
//  [local softmax] [attended partial] csync3 [gates GEMV] csync4 [h update]
__global__ void __launch_bounds__(512, 1) __cluster_dims__(2, 1, 1)
fused_kernel(const float* __restrict__ x,   const float* __restrict__ Wg,
             const float* __restrict__ Wc,  const float* __restrict__ bias,
             const float* __restrict__ u,   const float* __restrict__ Wx,
             const float* __restrict__ Wh,  const float* __restrict__ bg,
             float* __restrict__ out)
{
    extern __shared__ float sm[];
    const int tid  = threadIdx.x;
    const int lane = tid & 31;
    const int wid  = tid >> 5;
    uint32_t rank; asm("mov.u32 %0, %%cluster_ctarank;" : "=r"(rank));
    const uint32_t peer = rank ^ 1u;
    const int r = (int)rank;
    const int b = blockIdx.x >> 1;

    // ---- prologue ----
    // zero WT2 (incl. pad columns 100..111 -> they contribute 0 to the GEMM)
    for (int i = tid; i < 11200; i += 512) sm[OFF_WT2 + i] = 0.0f;
    for (int i = tid; i < 15000; i += 512) sm[OFF_WX + i] = Wx[r * 15000 + i];
    for (int i = tid; i < 15000; i += 512) sm[OFF_WH + i] = Wh[r * 15000 + i];
    for (int i = tid; i <  5000; i += 512) sm[OFF_WC + i] = Wc[r *  5000 + i];
    if (tid < 100) { sm[OFF_U + tid] = u[tid]; sm[OFF_BIAS + tid] = bias[tid];
                     sm[OFF_H + tid] = 0.0f; }
    if (tid < 300)   sm[OFF_BG + tid] = bg[tid];
    __syncthreads();
    // build pair-transposed W: Wt2[gp][f] = (W[2gp][f], W[2gp+1][f])
    for (int i = tid; i < 5000; i += 512) {
        const int gp = i / 100, f = i % 100;
        float2 v = make_float2(Wg[(2 * gp) * 100 + f], Wg[(2 * gp + 1) * 100 + f]);
        *reinterpret_cast<float2*>(&sm[OFF_WT2 + 2 * (gp * 112 + f)]) = v;
    }

    const float* xbase = x + (size_t)b * Sn * Tn * Fn + (size_t)r * THALF * Fn;
    float*       ob    = out + (size_t)b * Sn * Fn;

    // stage x tile for s=0 into RAW0 (12800 B = 800 x 16B)
    {
        const uint32_t dst = s2u(sm + OFF_RAW0);
        for (int c = tid; c < 800; c += 512)
            asm volatile("cp.async.cg.shared.global [%0], [%1], 16;"
                         :: "r"(dst + c * 16), "l"(xbase + c * 4));
        asm volatile("cp.async.commit_group;" ::: "memory");
    }
    __syncthreads();   // WT2 build complete before first GEMM

    ull acc[4][7];     // X-GEMM accumulators (live only on warps 0-3 paths)

    for (int s = 0; s < Sn; ++s) {
        asm volatile("cp.async.wait_group 0;" ::: "memory");
        __syncthreads();            // raw[s&1] ready; h(s-1), WT2 visible

        const float* rawp = sm + ((s & 1) ? OFF_RAW1 : OFF_RAW0);

        // prefetch x(s+1) into the other buffer (overlaps whole step)
        if (s + 1 < Sn) {
            const uint32_t dst = s2u(sm + (((s + 1) & 1) ? OFF_RAW1 : OFF_RAW0));
            const float* src = xbase + (size_t)(s + 1) * Tn * Fn;
            for (int c = tid; c < 800; c += 512)
                asm volatile("cp.async.cg.shared.global [%0], [%1], 16;"
                             :: "r"(dst + c * 16), "l"(src + c * 4));
        }
        asm volatile("cp.async.commit_group;" ::: "memory");

        // ---- warps 0-3: X-GEMM (g-pair f32x2, 8 t-rows/warp, 2 subgroups) --
        //      warps 4-15: gh = h@Wh partial, c = h@Wc partial --
        if (wid < 4) {
            const int sg = lane >> 4, ls = lane & 15;
            const int tb = wid * 8 + sg * 4;
            const ull* xr = reinterpret_cast<const ull*>(rawp);      // [t*50+gp]
            const ull* wr = reinterpret_cast<const ull*>(sm) + ls;   // WT2 base+ls
#pragma unroll
            for (int ti = 0; ti < 4; ++ti)
#pragma unroll
                for (int k = 0; k < 7; ++k) acc[ti][k] = 0ull;
            for (int gp = 0; gp < 50; ++gp) {
                const ull* wrow = wr + gp * 112;
                const ull w0 = wrow[0],  w1 = wrow[16], w2 = wrow[32],
                          w3 = wrow[48], w4 = wrow[64], w5 = wrow[80],
                          w6 = wrow[96];                 // pad -> 0 for ls>=4
                const ull x0 = xr[(tb + 0) * 50 + gp];
                const ull x1 = xr[(tb + 1) * 50 + gp];
                const ull x2 = xr[(tb + 2) * 50 + gp];
                const ull x3 = xr[(tb + 3) * 50 + gp];
#define XSTEP(ti, xv) \
                acc[ti][0] = ffma2(xv, w0, acc[ti][0]); \
                acc[ti][1] = ffma2(xv, w1, acc[ti][1]); \
                acc[ti][2] = ffma2(xv, w2, acc[ti][2]); \
                acc[ti][3] = ffma2(xv, w3, acc[ti][3]); \
                acc[ti][4] = ffma2(xv, w4, acc[ti][4]); \
                acc[ti][5] = ffma2(xv, w5, acc[ti][5]); \
                acc[ti][6] = ffma2(xv, w6, acc[ti][6]);
                XSTEP(0, x0) XSTEP(1, x1) XSTEP(2, x2) XSTEP(3, x3)
#undef XSTEP
            }
        } else {
            const int t2 = tid - 128;          // 0..383
            if (t2 < 300) {
                const int j = t2;
                float a0 = 0.0f, a1 = 0.0f;
#pragma unroll 5
                for (int gl = 0; gl < 50; gl += 2) {
                    a0 += sm[OFF_H + 50 * r + gl    ] * sm[OFF_WH + gl       * F3 + j];
                    a1 += sm[OFF_H + 50 * r + gl + 1] * sm[OFF_WH + (gl + 1) * F3 + j];
                }
                const float v = a0 + a1;
                sm[OFF_GHP + j] = v;
                st_peer(&sm[OFF_GHQ + (s & 1) * F3 + j], peer, v);
            } else {
                for (int f = t2 - 300; f < 100; f += 84) {
                    float a0 = 0.0f, a1 = 0.0f;
#pragma unroll 5
                    for (int gl = 0; gl < 50; gl += 2) {
                        a0 += sm[OFF_H + 50 * r + gl    ] * sm[OFF_WC + gl       * Fn + f];
                        a1 += sm[OFF_H + 50 * r + gl + 1] * sm[OFF_WC + (gl + 1) * Fn + f];
                    }
                    const float v = a0 + a1;
                    sm[OFF_CP + f] = v;
                    st_peer(&sm[OFF_CQ + f], peer, v);
                }
            }
        }
        CLUSTER_SYNC();   // #1: gh & c partials exchanged

        // ---- Phase B (warps 0-3): scores from register-resident xw ----
        if (wid < 4) {
            const int sg = lane >> 4, ls = lane & 15;
            const int tb = wid * 8 + sg * 4;
#pragma unroll
            for (int ti = 0; ti < 4; ++ti) {
                float p = 0.0f;
#pragma unroll
                for (int k = 0; k < 7; ++k) {
                    if (k < 6 || ls < 4) {
                        const int f = ls + 16 * k;
                        const float xw =
                            __uint_as_float((unsigned)(acc[ti][k] & 0xffffffffull))
                          + __uint_as_float((unsigned)(acc[ti][k] >> 32))
                          + sm[OFF_BIAS + f];
                        p += tanh_ap(xw + sm[OFF_CP + f] + sm[OFF_CQ + f])
                             * sm[OFF_U + f];
                    }
                }
#pragma unroll
                for (int o = 8; o; o >>= 1)
                    p += __shfl_xor_sync(0xffffffffu, p, o, 16);
                if (ls == 0) {
                    sm[OFF_ALOC + tb + ti] = p;
                    st_peer(&sm[OFF_APEER + tb + ti], peer, p);
                }
            }
        }
        CLUSTER_SYNC();   // #2: raw scores exchanged

        // ---- local softmax (warp 15): global denom, weights for own 32 t ----
        if (wid == 15) {
            const float eo = __expf(sm[OFF_ALOC + lane]);
            const float ep = __expf(sm[OFF_APEER + lane]);
            float tot = eo + ep;
#pragma unroll
            for (int o = 16; o; o >>= 1)
                tot += __shfl_xor_sync(0xffffffffu, tot, o);
            sm[OFF_EW + lane] = eo / (tot + EPSV);
        }
        __syncthreads();

        // ---- Phase C: attended partial over my 32 t-rows ----
        if (tid < Fn) {
            float a0 = 0.f, a1 = 0.f, a2 = 0.f, a3 = 0.f;
#pragma unroll 4
            for (int t = 0; t < THALF; t += 4) {
                a0 += sm[OFF_EW + t    ] * rawp[(t    ) * Fn + tid];
                a1 += sm[OFF_EW + t + 1] * rawp[(t + 1) * Fn + tid];
                a2 += sm[OFF_EW + t + 2] * rawp[(t + 2) * Fn + tid];
                a3 += sm[OFF_EW + t + 3] * rawp[(t + 3) * Fn + tid];
            }
            const float v = (a0 + a1) + (a2 + a3);
            sm[OFF_ATTP + tid] = v;
            st_peer(&sm[OFF_ATTQ + tid], peer, v);
        }
        CLUSTER_SYNC();   // #3: attended partials exchanged

        // ---- Phase D: gx partial = att @ Wx over my 50 K-rows ----
        if (tid < F3) {
            float acc2 = (r == 0) ? sm[OFF_BG + tid] : 0.0f;
#pragma unroll 2
            for (int gl = 0; gl < 50; ++gl) {
                const int g = 50 * r + gl;
                const float af = sm[OFF_ATTP + g] + sm[OFF_ATTQ + g];
                acc2 += af * sm[OFF_WX + gl * F3 + tid];
            }
            sm[OFF_GXP + tid] = acc2;
            st_peer(&sm[OFF_GXQ + tid], peer, acc2);
        }
        CLUSTER_SYNC();   // #4: gx partials exchanged

        // ---- final: gates + h update (redundant in both CTAs) ----
        if (tid < Fn) {
            const int f  = tid;
            const int gq = OFF_GHQ + (s & 1) * F3;
            const float gz  = sm[OFF_GHP + f]       + sm[gq + f]
                            + sm[OFF_GXP + f]       + sm[OFF_GXQ + f];
            const float gr  = sm[OFF_GHP + 100 + f] + sm[gq + 100 + f]
                            + sm[OFF_GXP + 100 + f] + sm[OFF_GXQ + 100 + f];
            const float ghc = sm[OFF_GHP + 200 + f] + sm[gq + 200 + f];
            const float gxc = sm[OFF_GXP + 200 + f] + sm[OFF_GXQ + 200 + f];
            const float z   = 1.0f / (1.0f + __expf(-gz));
            const float rr  = 1.0f / (1.0f + __expf(-gr));
            const float ht  = tanhf(gxc + rr * ghc);
            const float hn  = (1.0f - z) * sm[OFF_H + f] + z * ht;
            sm[OFF_H + f] = hn;
            if (r == 0) ob[s * Fn + f] = hn;
        }
        // next-step visibility of h covered by top-of-loop __syncthreads;
        // cross-CTA GHQ hazard covered by parity double-buffer.
    }
}

// ---------------------------------------------------------------------------
extern "C" void kernel_launch(void* const* d_in, const int* in_sizes, int n_in,
                              void* d_out, int out_size) {
    const float* x   = (const float*)d_in[0];
    const float* W   = (const float*)d_in[1];
    const float* Wc  = (const float*)d_in[2];
    const float* bb  = (const float*)d_in[3];
    const float* u   = (const float*)d_in[4];
    const float* Wx  = (const float*)d_in[5];
    const float* Wh  = (const float*)d_in[6];
    const float* bg  = (const float*)d_in[7];
    float* out = (float*)d_out;

    const int smem = SMEM_FLOATS * 4;   // 220,800 B
    cudaFuncSetAttribute(fused_kernel,
                         cudaFuncAttributeMaxDynamicSharedMemorySize, smem);
    fused_kernel<<<2 * Bn, 512, smem>>>(x, W, Wc, bb, u, Wx, Wh, bg, out);
}